// round 10
// baseline (speedup 1.0000x reference)
#include <cuda_runtime.h>
#include <cuda_fp16.h>
#include <stdint.h>

#define P1C 2654435761u
#define P2C 805459861u

// smem dense grids for levels 0,1 as scaled half2: 17^3 + 23^3 entries
#define CAP0 4913
#define CAP1 12167
#define COARSE_SMEM ((CAP0 + CAP1) * 4)   // 68,320 B
#define COARSE_BLOCKS 64
#define COARSE_TPB 256
#define HSCALE 1024.0f
#define HINV   (1.0f / 1024.0f)

__device__ __forceinline__ uint32_t f2u(float f) {
    return (uint32_t)(int32_t)f;
}

// Streaming (evict-first) stores for write-once output.
__device__ __forceinline__ void st_cs_f2(float2* p, float2 v) {
    asm volatile("st.global.cs.v2.f32 [%0], {%1, %2};"
                 :: "l"(p), "f"(v.x), "f"(v.y) : "memory");
}
__device__ __forceinline__ void st_cs_f4(float4* p, float4 v) {
    asm volatile("st.global.cs.v4.f32 [%0], {%1, %2, %3, %4};"
                 :: "l"(p), "f"(v.x), "f"(v.y), "f"(v.z), "f"(v.w) : "memory");
}

// ---------------------------------------------------------------------------
// Fine kernel: levels 2..15, one thread per (point, level).
// blockDim = 224 = 16 points * 14 levels.  (137.5us measured — FROZEN)
// ---------------------------------------------------------------------------
__global__ void __launch_bounds__(224)
hashenc_fine(const float* __restrict__ x,
             const float2* __restrict__ table,
             const float* __restrict__ scalings,
             const int* __restrict__ hash_offset,
             const int* __restrict__ tsp, int ts_flag,
             float2* __restrict__ out,
             int n_points)
{
    int local = threadIdx.x;
    int pib   = local / 14;               // point in block [0,16)
    int level = 2 + (local - pib * 14);   // [2,16)
    int point = blockIdx.x * 16 + pib;
    if (point >= n_points) return;

    uint32_t ts = ts_flag ? (uint32_t)__ldg(tsp) : 524288u;
    bool pow2 = (ts & (ts - 1u)) == 0u;
    uint32_t mask = ts - 1u;

    float px = __ldg(&x[point * 3 + 0]);
    float py = __ldg(&x[point * 3 + 1]);
    float pz = __ldg(&x[point * 3 + 2]);

    float s = __ldg(&scalings[level]);
    int  off = __ldg(&hash_offset[level]);

    float sx = px * s, sy = py * s, sz = pz * s;
    float fx = floorf(sx), fy = floorf(sy), fz = floorf(sz);
    float cx = ceilf(sx), cy = ceilf(sy), cz = ceilf(sz);
    float tx = sx - fx, ty = sy - fy, tz = sz - fz;

    uint32_t axf = f2u(fx);
    uint32_t axc = f2u(cx);
    uint32_t hyf = f2u(fy) * P1C;
    uint32_t hyc = f2u(cy) * P1C;
    uint32_t hzf = f2u(fz) * P2C;
    uint32_t hzc = f2u(cz) * P2C;

    float ux = 1.0f - tx, uy = 1.0f - ty, uz = 1.0f - tz;
    // EXACT reference weight<->corner pairing (tz quirk preserved)
    float w0 = tx * ty * tz;   // (c,c,c)
    float w1 = tx * uy * tz;   // (c,c,f)
    float w2 = ux * uy * tz;   // (c,f,c)
    float w3 = ux * ty * tz;   // (f,c,c)
    float w4 = tx * ty * uz;   // (c,f,f)
    float w5 = tx * uy * uz;   // (f,c,f)
    float w6 = ux * uy * uz;   // (f,f,c)
    float w7 = ux * ty * uz;   // (f,f,f)

    float ex = 0.f, ey = 0.f;

    if (pow2 && ((axf ^ axc) == 1u)) {
        // x floor/ceil pair shares one aligned 16B float4 chunk.
        const float4* __restrict__ t4 = (const float4*)table;
        uint32_t off2 = ((uint32_t)off) >> 1;

        uint32_t b0 = hyc ^ hzc;   // pair (v0 ceil-x, v3 floor-x)
        uint32_t b1 = hyc ^ hzf;   // pair (v1, v5)
        uint32_t b2 = hyf ^ hzc;   // pair (v2, v6)
        uint32_t b3 = hyf ^ hzf;   // pair (v4, v7)

        uint32_t i0 = (axf ^ b0) & mask;
        uint32_t i1 = (axf ^ b1) & mask;
        uint32_t i2 = (axf ^ b2) & mask;
        uint32_t i3 = (axf ^ b3) & mask;

        float4 q0 = __ldg(&t4[(i0 >> 1) + off2]);
        float4 q1 = __ldg(&t4[(i1 >> 1) + off2]);
        float4 q2 = __ldg(&t4[(i2 >> 1) + off2]);
        float4 q3 = __ldg(&t4[(i3 >> 1) + off2]);

        {
            uint32_t sel = i0 & 1u;
            float ffx = sel ? q0.z : q0.x, ffy = sel ? q0.w : q0.y;
            float fcx = sel ? q0.x : q0.z, fcy = sel ? q0.y : q0.w;
            ex = fmaf(w3, ffx, ex); ey = fmaf(w3, ffy, ey);
            ex = fmaf(w0, fcx, ex); ey = fmaf(w0, fcy, ey);
        }
        {
            uint32_t sel = i1 & 1u;
            float ffx = sel ? q1.z : q1.x, ffy = sel ? q1.w : q1.y;
            float fcx = sel ? q1.x : q1.z, fcy = sel ? q1.y : q1.w;
            ex = fmaf(w5, ffx, ex); ey = fmaf(w5, ffy, ey);
            ex = fmaf(w1, fcx, ex); ey = fmaf(w1, fcy, ey);
        }
        {
            uint32_t sel = i2 & 1u;
            float ffx = sel ? q2.z : q2.x, ffy = sel ? q2.w : q2.y;
            float fcx = sel ? q2.x : q2.z, fcy = sel ? q2.y : q2.w;
            ex = fmaf(w6, ffx, ex); ey = fmaf(w6, ffy, ey);
            ex = fmaf(w2, fcx, ex); ey = fmaf(w2, fcy, ey);
        }
        {
            uint32_t sel = i3 & 1u;
            float ffx = sel ? q3.z : q3.x, ffy = sel ? q3.w : q3.y;
            float fcx = sel ? q3.x : q3.z, fcy = sel ? q3.y : q3.w;
            ex = fmaf(w7, ffx, ex); ey = fmaf(w7, ffy, ey);
            ex = fmaf(w4, fcx, ex); ey = fmaf(w4, fcy, ey);
        }
    } else {
        uint32_t h0 = axc ^ hyc ^ hzc;
        uint32_t h1 = axc ^ hyc ^ hzf;
        uint32_t h2 = axc ^ hyf ^ hzc;
        uint32_t h3 = axf ^ hyc ^ hzc;
        uint32_t h4 = axc ^ hyf ^ hzf;
        uint32_t h5 = axf ^ hyc ^ hzf;
        uint32_t h6 = axf ^ hyf ^ hzc;
        uint32_t h7 = axf ^ hyf ^ hzf;

        int i0, i1, i2, i3, i4, i5, i6, i7;
        if (pow2) {
            i0 = (int)(h0 & mask) + off;  i1 = (int)(h1 & mask) + off;
            i2 = (int)(h2 & mask) + off;  i3 = (int)(h3 & mask) + off;
            i4 = (int)(h4 & mask) + off;  i5 = (int)(h5 & mask) + off;
            i6 = (int)(h6 & mask) + off;  i7 = (int)(h7 & mask) + off;
        } else {
            i0 = (int)(h0 % ts) + off;    i1 = (int)(h1 % ts) + off;
            i2 = (int)(h2 % ts) + off;    i3 = (int)(h3 % ts) + off;
            i4 = (int)(h4 % ts) + off;    i5 = (int)(h5 % ts) + off;
            i6 = (int)(h6 % ts) + off;    i7 = (int)(h7 % ts) + off;
        }

        float2 f0 = __ldg(&table[i0]);
        float2 f1 = __ldg(&table[i1]);
        float2 f2 = __ldg(&table[i2]);
        float2 f3 = __ldg(&table[i3]);
        float2 f4 = __ldg(&table[i4]);
        float2 f5 = __ldg(&table[i5]);
        float2 f6 = __ldg(&table[i6]);
        float2 f7 = __ldg(&table[i7]);

        ex = fmaf(w0, f0.x, ex); ey = fmaf(w0, f0.y, ey);
        ex = fmaf(w1, f1.x, ex); ey = fmaf(w1, f1.y, ey);
        ex = fmaf(w2, f2.x, ex); ey = fmaf(w2, f2.y, ey);
        ex = fmaf(w3, f3.x, ex); ey = fmaf(w3, f3.y, ey);
        ex = fmaf(w4, f4.x, ex); ey = fmaf(w4, f4.y, ey);
        ex = fmaf(w5, f5.x, ex); ey = fmaf(w5, f5.y, ey);
        ex = fmaf(w6, f6.x, ex); ey = fmaf(w6, f6.y, ey);
        ex = fmaf(w7, f7.x, ex); ey = fmaf(w7, f7.y, ey);
    }

    st_cs_f2(&out[point * 16 + level], make_float2(ex, ey));
}

// ---------------------------------------------------------------------------
// Coarse kernel: levels 0..1 via smem-resident dense grids in SCALED HALF2.
// Halves LDS bytes vs fp32 and shrinks the smem carveout 137KB -> 68KB so
// co-resident fine CTAs on these 64 SMs keep more L1D.
// ---------------------------------------------------------------------------
__global__ void __launch_bounds__(COARSE_TPB)
hashenc_coarse(const float* __restrict__ x,
               const float2* __restrict__ table,
               const float* __restrict__ scalings,
               const int* __restrict__ hash_offset,
               const int* __restrict__ tsp, int ts_flag,
               float2* __restrict__ out,
               int n_points, int pts_per_cta)
{
    extern __shared__ __half2 sm[];   // [n0 + n1]

    uint32_t ts = ts_flag ? (uint32_t)__ldg(tsp) : 524288u;
    bool pow2 = (ts & (ts - 1u)) == 0u;
    uint32_t mask = ts - 1u;

    float s0 = __ldg(&scalings[0]);
    float s1 = __ldg(&scalings[1]);
    int off0 = __ldg(&hash_offset[0]);
    int off1 = __ldg(&hash_offset[1]);
    int d0 = (int)s0 + 1;
    int d1 = (int)s1 + 1;
    int n0 = d0 * d0 * d0;
    int n1 = d1 * d1 * d1;

    int tid = threadIdx.x;
    int p_begin = blockIdx.x * pts_per_cta;
    int p_end = p_begin + pts_per_cta;
    if (p_end > n_points) p_end = n_points;

    bool ok = (n0 <= CAP0) && (n1 <= CAP1) && (d0 > 1) && (d1 > 1);

    if (ok) {
        const float4* __restrict__ t4 = (const float4*)table;
        // --- preload levels 0,1 (paired LDG.128 when pow2) ---
        #pragma unroll
        for (int l = 0; l < 2; l++) {
            int d = l ? d1 : d0;
            int off = l ? off1 : off0;
            __half2* g = sm + (l ? n0 : 0);
            if (pow2) {
                int ppr = d >> 1;
                int npairs = d * d * ppr;
                uint32_t off2 = ((uint32_t)off) >> 1;
                for (int id = tid; id < npairs; id += COARSE_TPB) {
                    int rowid = id / ppr;
                    int gx = (id - rowid * ppr) * 2;
                    int gy = rowid % d;
                    int gz = rowid / d;
                    uint32_t h = ((uint32_t)gx ^ ((uint32_t)gy * P1C) ^ ((uint32_t)gz * P2C)) & mask;
                    float4 q = __ldg(&t4[(h >> 1) + off2]);
                    int base = (gz * d + gy) * d + gx;
                    bool hodd = h & 1u;
                    float2 e0 = hodd ? make_float2(q.z, q.w) : make_float2(q.x, q.y);
                    float2 e1 = hodd ? make_float2(q.x, q.y) : make_float2(q.z, q.w);
                    g[base]     = __floats2half2_rn(e0.x * HSCALE, e0.y * HSCALE);
                    g[base + 1] = __floats2half2_rn(e1.x * HSCALE, e1.y * HSCALE);
                }
                if (d & 1) {   // last column when d is odd
                    int gx = d - 1;
                    for (int id = tid; id < d * d; id += COARSE_TPB) {
                        int gy = id % d, gz = id / d;
                        uint32_t h = ((uint32_t)gx ^ ((uint32_t)gy * P1C) ^ ((uint32_t)gz * P2C)) & mask;
                        float2 f = __ldg(&table[(int)h + off]);
                        g[(gz * d + gy) * d + gx] = __floats2half2_rn(f.x * HSCALE, f.y * HSCALE);
                    }
                }
            } else {
                int n = d * d * d;
                for (int id = tid; id < n; id += COARSE_TPB) {
                    int gz = id / (d * d);
                    int r  = id - gz * d * d;
                    int gy = r / d;
                    int gx = r - gy * d;
                    uint32_t h = ((uint32_t)gx ^ ((uint32_t)gy * P1C) ^ ((uint32_t)gz * P2C)) % ts;
                    float2 f = __ldg(&table[(int)h + off]);
                    g[id] = __floats2half2_rn(f.x * HSCALE, f.y * HSCALE);
                }
            }
        }
        __syncthreads();

        for (int p = p_begin + tid; p < p_end; p += COARSE_TPB) {
            float px = __ldg(&x[p * 3 + 0]);
            float py = __ldg(&x[p * 3 + 1]);
            float pz = __ldg(&x[p * 3 + 2]);

            float2 res[2];
            #pragma unroll
            for (int l = 0; l < 2; l++) {
                float s = l ? s1 : s0;
                int dim = l ? d1 : d0;
                const __half2* __restrict__ g = sm + (l ? n0 : 0);

                float sx = px * s, sy = py * s, sz = pz * s;
                float fx = floorf(sx), fy = floorf(sy), fz = floorf(sz);
                float cxx = ceilf(sx), cyy = ceilf(sy), czz = ceilf(sz);
                float tx = sx - fx, ty = sy - fy, tz = sz - fz;

                int gxf = (int)fx, gxc = (int)cxx;
                int gyf = (int)fy, gyc = (int)cyy;
                int gzf = (int)fz, gzc = (int)czz;

                int ryc_zc = (gzc * dim + gyc) * dim;
                int ryc_zf = (gzf * dim + gyc) * dim;
                int ryf_zc = (gzc * dim + gyf) * dim;
                int ryf_zf = (gzf * dim + gyf) * dim;

                float2 f0 = __half22float2(g[ryc_zc + gxc]);   // (c,c,c)
                float2 f1 = __half22float2(g[ryc_zf + gxc]);   // (c,c,f)
                float2 f2 = __half22float2(g[ryf_zc + gxc]);   // (c,f,c)
                float2 f3 = __half22float2(g[ryc_zc + gxf]);   // (f,c,c)
                float2 f4 = __half22float2(g[ryf_zf + gxc]);   // (c,f,f)
                float2 f5 = __half22float2(g[ryc_zf + gxf]);   // (f,c,f)
                float2 f6 = __half22float2(g[ryf_zc + gxf]);   // (f,f,c)
                float2 f7 = __half22float2(g[ryf_zf + gxf]);   // (f,f,f)

                float ux = 1.0f - tx, uy = 1.0f - ty, uz = 1.0f - tz;
                float w0 = tx * ty * tz;
                float w1 = tx * uy * tz;
                float w2 = ux * uy * tz;
                float w3 = ux * ty * tz;
                float w4 = tx * ty * uz;
                float w5 = tx * uy * uz;
                float w6 = ux * uy * uz;
                float w7 = ux * ty * uz;

                float ex = 0.f, ey = 0.f;
                ex = fmaf(w0, f0.x, ex); ey = fmaf(w0, f0.y, ey);
                ex = fmaf(w1, f1.x, ex); ey = fmaf(w1, f1.y, ey);
                ex = fmaf(w2, f2.x, ex); ey = fmaf(w2, f2.y, ey);
                ex = fmaf(w3, f3.x, ex); ey = fmaf(w3, f3.y, ey);
                ex = fmaf(w4, f4.x, ex); ey = fmaf(w4, f4.y, ey);
                ex = fmaf(w5, f5.x, ex); ey = fmaf(w5, f5.y, ey);
                ex = fmaf(w6, f6.x, ex); ey = fmaf(w6, f6.y, ey);
                ex = fmaf(w7, f7.x, ex); ey = fmaf(w7, f7.y, ey);
                res[l] = make_float2(ex * HINV, ey * HINV);
            }
            // two adjacent float2 -> one streaming float4 store
            st_cs_f4((float4*)(out + p * 16),
                     make_float4(res[0].x, res[0].y, res[1].x, res[1].y));
        }
    } else {
        // Fallback: global gathers for levels 0..1 (any table size / scaling)
        for (int p = p_begin + tid; p < p_end; p += COARSE_TPB) {
            float px = __ldg(&x[p * 3 + 0]);
            float py = __ldg(&x[p * 3 + 1]);
            float pz = __ldg(&x[p * 3 + 2]);
            #pragma unroll
            for (int l = 0; l < 2; l++) {
                float s = l ? s1 : s0;
                int off = l ? off1 : off0;
                float sx = px * s, sy = py * s, sz = pz * s;
                float fx = floorf(sx), fy = floorf(sy), fz = floorf(sz);
                float cxx = ceilf(sx), cyy = ceilf(sy), czz = ceilf(sz);
                float tx = sx - fx, ty = sy - fy, tz = sz - fz;

                uint32_t axf = f2u(fx), axc = f2u(cxx);
                uint32_t hyf = f2u(fy) * P1C, hyc = f2u(cyy) * P1C;
                uint32_t hzf = f2u(fz) * P2C, hzc = f2u(czz) * P2C;

                uint32_t hs[8] = {
                    axc ^ hyc ^ hzc, axc ^ hyc ^ hzf, axc ^ hyf ^ hzc, axf ^ hyc ^ hzc,
                    axc ^ hyf ^ hzf, axf ^ hyc ^ hzf, axf ^ hyf ^ hzc, axf ^ hyf ^ hzf };

                float ux = 1.0f - tx, uy = 1.0f - ty, uz = 1.0f - tz;
                float w[8] = {
                    tx * ty * tz, tx * uy * tz, ux * uy * tz, ux * ty * tz,
                    tx * ty * uz, tx * uy * uz, ux * uy * uz, ux * ty * uz };

                float ex = 0.f, ey = 0.f;
                #pragma unroll
                for (int c = 0; c < 8; c++) {
                    int idx = (int)(hs[c] % ts) + off;
                    float2 f = __ldg(&table[idx]);
                    ex = fmaf(w[c], f.x, ex);
                    ey = fmaf(w[c], f.y, ey);
                }
                st_cs_f2(&out[p * 16 + l], make_float2(ex, ey));
            }
        }
    }
}

// ---------------------------------------------------------------------------
// Generic fallback (L != 16)
// ---------------------------------------------------------------------------
__global__ void __launch_bounds__(256)
hashenc_kernel_gen(const float* __restrict__ x,
                   const float2* __restrict__ table,
                   const float* __restrict__ scalings,
                   const int* __restrict__ hash_offset,
                   const int* __restrict__ tsp, int ts_flag,
                   float2* __restrict__ out,
                   int n_points, int L)
{
    int tid = blockIdx.x * 256 + threadIdx.x;
    int level = tid % L;
    int point = tid / L;
    if (point >= n_points) return;

    uint32_t ts = ts_flag ? (uint32_t)__ldg(tsp) : 524288u;

    float px = __ldg(&x[point * 3 + 0]);
    float py = __ldg(&x[point * 3 + 1]);
    float pz = __ldg(&x[point * 3 + 2]);

    float s = __ldg(&scalings[level]);
    int  off = __ldg(&hash_offset[level]);

    float sx = px * s, sy = py * s, sz = pz * s;
    float fx = floorf(sx), fy = floorf(sy), fz = floorf(sz);
    float cx = ceilf(sx), cy = ceilf(sy), cz = ceilf(sz);
    float tx = sx - fx, ty = sy - fy, tz = sz - fz;

    uint32_t hxf = f2u(fx), hxc = f2u(cx);
    uint32_t hyf = f2u(fy) * P1C, hyc = f2u(cy) * P1C;
    uint32_t hzf = f2u(fz) * P2C, hzc = f2u(cz) * P2C;

    uint32_t hs[8] = {
        hxc ^ hyc ^ hzc, hxc ^ hyc ^ hzf, hxc ^ hyf ^ hzc, hxf ^ hyc ^ hzc,
        hxc ^ hyf ^ hzf, hxf ^ hyc ^ hzf, hxf ^ hyf ^ hzc, hxf ^ hyf ^ hzf };

    float ux = 1.0f - tx, uy = 1.0f - ty, uz = 1.0f - tz;
    float w[8] = {
        tx * ty * tz, tx * uy * tz, ux * uy * tz, ux * ty * tz,
        tx * ty * uz, tx * uy * uz, ux * uy * uz, ux * ty * uz };

    float ex = 0.f, ey = 0.f;
    #pragma unroll
    for (int c = 0; c < 8; c++) {
        int idx = (int)(hs[c] % ts) + off;
        float2 f = __ldg(&table[idx]);
        ex = fmaf(w[c], f.x, ex);
        ey = fmaf(w[c], f.y, ey);
    }
    out[point * L + level] = make_float2(ex, ey);
}

extern "C" void kernel_launch(void* const* d_in, const int* in_sizes, int n_in,
                              void* d_out, int out_size)
{
    const float*  x        = (const float*)d_in[0];
    const float2* table    = (const float2*)d_in[1];
    const float*  scalings = (const float*)d_in[2];
    const int*    hoff     = (const int*)d_in[3];
    const int*    tsp      = (n_in >= 5) ? (const int*)d_in[4] : nullptr;
    int ts_flag = (tsp != nullptr) ? 1 : 0;

    int n_points = in_sizes[0] / 3;
    int L = in_sizes[2];

    float2* out = (float2*)d_out;

    if (L == 16) {
        static bool attr_set = false;
        if (!attr_set) {
            cudaFuncSetAttribute(hashenc_coarse,
                                 cudaFuncAttributeMaxDynamicSharedMemorySize,
                                 COARSE_SMEM);
            attr_set = true;
        }

        // Fork a side stream off the capturing main stream so coarse runs
        // concurrently with fine (R8-proven structure).
        cudaStream_t s2;
        cudaEvent_t e1, e2;
        cudaStreamCreateWithFlags(&s2, cudaStreamNonBlocking);
        cudaEventCreateWithFlags(&e1, cudaEventDisableTiming);
        cudaEventCreateWithFlags(&e2, cudaEventDisableTiming);

        cudaEventRecord(e1, 0);
        cudaStreamWaitEvent(s2, e1, 0);

        int pts_per_cta = (n_points + COARSE_BLOCKS - 1) / COARSE_BLOCKS;
        hashenc_coarse<<<COARSE_BLOCKS, COARSE_TPB, COARSE_SMEM, s2>>>(
            x, table, scalings, hoff, tsp, ts_flag, out, n_points, pts_per_cta);

        int fine_blocks = (n_points + 15) / 16;
        hashenc_fine<<<fine_blocks, 224>>>(
            x, table, scalings, hoff, tsp, ts_flag, out, n_points);

        cudaEventRecord(e2, s2);
        cudaStreamWaitEvent(0, e2, 0);
    } else {
        long long total = (long long)n_points * L;
        int blocks = (int)((total + 255) / 256);
        hashenc_kernel_gen<<<blocks, 256>>>(x, table, scalings, hoff, tsp, ts_flag,
                                            out, n_points, L);
    }
}

// round 11
// speedup vs baseline: 1.2156x; 1.2156x over previous
#include <cuda_runtime.h>
#include <stdint.h>

#define P1C 2654435761u
#define P2C 805459861u

// smem dense grids for levels 0,1 (fp32 float2): 17^3 + 23^3
#define CAP0 4913
#define CAP1 12167
#define CAPT (CAP0 + CAP1)
#define COARSE_SMEM (CAPT * 8)
#define COARSE_BLOCKS 64
#define COARSE_TPB 256

// Staged (de-hashed) coarse grids, written once per launch by hashenc_stage,
// read coalesced by every coarse CTA. __device__ global: no allocation.
__device__ float2 g_stage[CAPT];

__device__ __forceinline__ uint32_t f2u(float f) {
    return (uint32_t)(int32_t)f;
}

// Streaming (evict-first) stores for write-once output.
__device__ __forceinline__ void st_cs_f2(float2* p, float2 v) {
    asm volatile("st.global.cs.v2.f32 [%0], {%1, %2};"
                 :: "l"(p), "f"(v.x), "f"(v.y) : "memory");
}
__device__ __forceinline__ void st_cs_f4(float4* p, float4 v) {
    asm volatile("st.global.cs.v4.f32 [%0], {%1, %2, %3, %4};"
                 :: "l"(p), "f"(v.x), "f"(v.y), "f"(v.z), "f"(v.w) : "memory");
}

// ---------------------------------------------------------------------------
// Fine kernel: levels 2..15, one thread per (point, level).
// blockDim = 224 = 16 points * 14 levels.  (137.5us measured — FROZEN)
// ---------------------------------------------------------------------------
__global__ void __launch_bounds__(224)
hashenc_fine(const float* __restrict__ x,
             const float2* __restrict__ table,
             const float* __restrict__ scalings,
             const int* __restrict__ hash_offset,
             const int* __restrict__ tsp, int ts_flag,
             float2* __restrict__ out,
             int n_points)
{
    int local = threadIdx.x;
    int pib   = local / 14;               // point in block [0,16)
    int level = 2 + (local - pib * 14);   // [2,16)
    int point = blockIdx.x * 16 + pib;
    if (point >= n_points) return;

    uint32_t ts = ts_flag ? (uint32_t)__ldg(tsp) : 524288u;
    bool pow2 = (ts & (ts - 1u)) == 0u;
    uint32_t mask = ts - 1u;

    float px = __ldg(&x[point * 3 + 0]);
    float py = __ldg(&x[point * 3 + 1]);
    float pz = __ldg(&x[point * 3 + 2]);

    float s = __ldg(&scalings[level]);
    int  off = __ldg(&hash_offset[level]);

    float sx = px * s, sy = py * s, sz = pz * s;
    float fx = floorf(sx), fy = floorf(sy), fz = floorf(sz);
    float cx = ceilf(sx), cy = ceilf(sy), cz = ceilf(sz);
    float tx = sx - fx, ty = sy - fy, tz = sz - fz;

    uint32_t axf = f2u(fx);
    uint32_t axc = f2u(cx);
    uint32_t hyf = f2u(fy) * P1C;
    uint32_t hyc = f2u(cy) * P1C;
    uint32_t hzf = f2u(fz) * P2C;
    uint32_t hzc = f2u(cz) * P2C;

    float ux = 1.0f - tx, uy = 1.0f - ty, uz = 1.0f - tz;
    // EXACT reference weight<->corner pairing (tz quirk preserved)
    float w0 = tx * ty * tz;   // (c,c,c)
    float w1 = tx * uy * tz;   // (c,c,f)
    float w2 = ux * uy * tz;   // (c,f,c)
    float w3 = ux * ty * tz;   // (f,c,c)
    float w4 = tx * ty * uz;   // (c,f,f)
    float w5 = tx * uy * uz;   // (f,c,f)
    float w6 = ux * uy * uz;   // (f,f,c)
    float w7 = ux * ty * uz;   // (f,f,f)

    float ex = 0.f, ey = 0.f;

    if (pow2 && ((axf ^ axc) == 1u)) {
        // x floor/ceil pair shares one aligned 16B float4 chunk.
        const float4* __restrict__ t4 = (const float4*)table;
        uint32_t off2 = ((uint32_t)off) >> 1;

        uint32_t b0 = hyc ^ hzc;   // pair (v0 ceil-x, v3 floor-x)
        uint32_t b1 = hyc ^ hzf;   // pair (v1, v5)
        uint32_t b2 = hyf ^ hzc;   // pair (v2, v6)
        uint32_t b3 = hyf ^ hzf;   // pair (v4, v7)

        uint32_t i0 = (axf ^ b0) & mask;
        uint32_t i1 = (axf ^ b1) & mask;
        uint32_t i2 = (axf ^ b2) & mask;
        uint32_t i3 = (axf ^ b3) & mask;

        float4 q0 = __ldg(&t4[(i0 >> 1) + off2]);
        float4 q1 = __ldg(&t4[(i1 >> 1) + off2]);
        float4 q2 = __ldg(&t4[(i2 >> 1) + off2]);
        float4 q3 = __ldg(&t4[(i3 >> 1) + off2]);

        {
            uint32_t sel = i0 & 1u;
            float ffx = sel ? q0.z : q0.x, ffy = sel ? q0.w : q0.y;
            float fcx = sel ? q0.x : q0.z, fcy = sel ? q0.y : q0.w;
            ex = fmaf(w3, ffx, ex); ey = fmaf(w3, ffy, ey);
            ex = fmaf(w0, fcx, ex); ey = fmaf(w0, fcy, ey);
        }
        {
            uint32_t sel = i1 & 1u;
            float ffx = sel ? q1.z : q1.x, ffy = sel ? q1.w : q1.y;
            float fcx = sel ? q1.x : q1.z, fcy = sel ? q1.y : q1.w;
            ex = fmaf(w5, ffx, ex); ey = fmaf(w5, ffy, ey);
            ex = fmaf(w1, fcx, ex); ey = fmaf(w1, fcy, ey);
        }
        {
            uint32_t sel = i2 & 1u;
            float ffx = sel ? q2.z : q2.x, ffy = sel ? q2.w : q2.y;
            float fcx = sel ? q2.x : q2.z, fcy = sel ? q2.y : q2.w;
            ex = fmaf(w6, ffx, ex); ey = fmaf(w6, ffy, ey);
            ex = fmaf(w2, fcx, ex); ey = fmaf(w2, fcy, ey);
        }
        {
            uint32_t sel = i3 & 1u;
            float ffx = sel ? q3.z : q3.x, ffy = sel ? q3.w : q3.y;
            float fcx = sel ? q3.x : q3.z, fcy = sel ? q3.y : q3.w;
            ex = fmaf(w7, ffx, ex); ey = fmaf(w7, ffy, ey);
            ex = fmaf(w4, fcx, ex); ey = fmaf(w4, fcy, ey);
        }
    } else {
        uint32_t h0 = axc ^ hyc ^ hzc;
        uint32_t h1 = axc ^ hyc ^ hzf;
        uint32_t h2 = axc ^ hyf ^ hzc;
        uint32_t h3 = axf ^ hyc ^ hzc;
        uint32_t h4 = axc ^ hyf ^ hzf;
        uint32_t h5 = axf ^ hyc ^ hzf;
        uint32_t h6 = axf ^ hyf ^ hzc;
        uint32_t h7 = axf ^ hyf ^ hzf;

        int i0, i1, i2, i3, i4, i5, i6, i7;
        if (pow2) {
            i0 = (int)(h0 & mask) + off;  i1 = (int)(h1 & mask) + off;
            i2 = (int)(h2 & mask) + off;  i3 = (int)(h3 & mask) + off;
            i4 = (int)(h4 & mask) + off;  i5 = (int)(h5 & mask) + off;
            i6 = (int)(h6 & mask) + off;  i7 = (int)(h7 & mask) + off;
        } else {
            i0 = (int)(h0 % ts) + off;    i1 = (int)(h1 % ts) + off;
            i2 = (int)(h2 % ts) + off;    i3 = (int)(h3 % ts) + off;
            i4 = (int)(h4 % ts) + off;    i5 = (int)(h5 % ts) + off;
            i6 = (int)(h6 % ts) + off;    i7 = (int)(h7 % ts) + off;
        }

        float2 f0 = __ldg(&table[i0]);
        float2 f1 = __ldg(&table[i1]);
        float2 f2 = __ldg(&table[i2]);
        float2 f3 = __ldg(&table[i3]);
        float2 f4 = __ldg(&table[i4]);
        float2 f5 = __ldg(&table[i5]);
        float2 f6 = __ldg(&table[i6]);
        float2 f7 = __ldg(&table[i7]);

        ex = fmaf(w0, f0.x, ex); ey = fmaf(w0, f0.y, ey);
        ex = fmaf(w1, f1.x, ex); ey = fmaf(w1, f1.y, ey);
        ex = fmaf(w2, f2.x, ex); ey = fmaf(w2, f2.y, ey);
        ex = fmaf(w3, f3.x, ex); ey = fmaf(w3, f3.y, ey);
        ex = fmaf(w4, f4.x, ex); ey = fmaf(w4, f4.y, ey);
        ex = fmaf(w5, f5.x, ex); ey = fmaf(w5, f5.y, ey);
        ex = fmaf(w6, f6.x, ex); ey = fmaf(w6, f6.y, ey);
        ex = fmaf(w7, f7.x, ex); ey = fmaf(w7, f7.y, ey);
    }

    st_cs_f2(&out[point * 16 + level], make_float2(ex, ey));
}

// ---------------------------------------------------------------------------
// Stage kernel: hash-gather each level-0/1 grid corner ONCE into g_stage
// (dense layout). Runs before hashenc_coarse on the same side stream.
// ---------------------------------------------------------------------------
__global__ void __launch_bounds__(256)
hashenc_stage(const float2* __restrict__ table,
              const float* __restrict__ scalings,
              const int* __restrict__ hash_offset,
              const int* __restrict__ tsp, int ts_flag)
{
    uint32_t ts = ts_flag ? (uint32_t)__ldg(tsp) : 524288u;
    bool pow2 = (ts & (ts - 1u)) == 0u;
    uint32_t mask = ts - 1u;

    float s0 = __ldg(&scalings[0]);
    float s1 = __ldg(&scalings[1]);
    int off0 = __ldg(&hash_offset[0]);
    int off1 = __ldg(&hash_offset[1]);
    int d0 = (int)s0 + 1;
    int d1 = (int)s1 + 1;
    int n0 = d0 * d0 * d0;
    int n1 = d1 * d1 * d1;

    if (!((n0 <= CAP0) && (n1 <= CAP1) && (d0 > 1) && (d1 > 1))) return;

    int total = n0 + n1;
    for (int id = blockIdx.x * 256 + threadIdx.x; id < total;
         id += gridDim.x * 256) {
        int l = (id < n0) ? 0 : 1;
        int local = id - (l ? n0 : 0);
        int d = l ? d1 : d0;
        int off = l ? off1 : off0;
        int gz = local / (d * d);
        int r  = local - gz * d * d;
        int gy = r / d;
        int gx = r - gy * d;
        uint32_t h = (uint32_t)gx ^ ((uint32_t)gy * P1C) ^ ((uint32_t)gz * P2C);
        h = pow2 ? (h & mask) : (h % ts);
        g_stage[id] = __ldg(&table[(int)h + off]);
    }
}

// ---------------------------------------------------------------------------
// Coarse kernel: levels 0..1 via smem-resident dense fp32 grids (R8-proven).
// Preload is now a COALESCED copy from g_stage (1068 lines/CTA instead of
// ~13K scattered gathers/CTA).
// ---------------------------------------------------------------------------
__global__ void __launch_bounds__(COARSE_TPB)
hashenc_coarse(const float* __restrict__ x,
               const float2* __restrict__ table,
               const float* __restrict__ scalings,
               const int* __restrict__ hash_offset,
               const int* __restrict__ tsp, int ts_flag,
               float2* __restrict__ out,
               int n_points, int pts_per_cta)
{
    extern __shared__ float2 sm[];   // [n0 + n1]

    uint32_t ts = ts_flag ? (uint32_t)__ldg(tsp) : 524288u;

    float s0 = __ldg(&scalings[0]);
    float s1 = __ldg(&scalings[1]);
    int off0 = __ldg(&hash_offset[0]);
    int off1 = __ldg(&hash_offset[1]);
    int d0 = (int)s0 + 1;
    int d1 = (int)s1 + 1;
    int n0 = d0 * d0 * d0;
    int n1 = d1 * d1 * d1;

    int tid = threadIdx.x;
    int p_begin = blockIdx.x * pts_per_cta;
    int p_end = p_begin + pts_per_cta;
    if (p_end > n_points) p_end = n_points;

    bool ok = (n0 <= CAP0) && (n1 <= CAP1) && (d0 > 1) && (d1 > 1);

    if (ok) {
        // --- coalesced preload from staged dense grids ---
        int total = n0 + n1;
        const float4* __restrict__ st4 = (const float4*)g_stage;
        float4* sm4 = (float4*)sm;
        int total4 = total >> 1;
        for (int id = tid; id < total4; id += COARSE_TPB)
            sm4[id] = __ldg(&st4[id]);
        if ((total & 1) && tid == 0)
            sm[total - 1] = g_stage[total - 1];
        __syncthreads();

        for (int p = p_begin + tid; p < p_end; p += COARSE_TPB) {
            float px = __ldg(&x[p * 3 + 0]);
            float py = __ldg(&x[p * 3 + 1]);
            float pz = __ldg(&x[p * 3 + 2]);

            float2 res[2];
            #pragma unroll
            for (int l = 0; l < 2; l++) {
                float s = l ? s1 : s0;
                int dim = l ? d1 : d0;
                const float2* base = l ? (sm + n0) : sm;

                float sx = px * s, sy = py * s, sz = pz * s;
                float fx = floorf(sx), fy = floorf(sy), fz = floorf(sz);
                float cxx = ceilf(sx), cyy = ceilf(sy), czz = ceilf(sz);
                float tx = sx - fx, ty = sy - fy, tz = sz - fz;

                int gxf = (int)fx, gxc = (int)cxx;
                int gyf = (int)fy, gyc = (int)cyy;
                int gzf = (int)fz, gzc = (int)czz;

                int ryc_zc = (gzc * dim + gyc) * dim;
                int ryc_zf = (gzf * dim + gyc) * dim;
                int ryf_zc = (gzc * dim + gyf) * dim;
                int ryf_zf = (gzf * dim + gyf) * dim;

                float2 f0 = base[ryc_zc + gxc];   // (c,c,c)
                float2 f1 = base[ryc_zf + gxc];   // (c,c,f)
                float2 f2 = base[ryf_zc + gxc];   // (c,f,c)
                float2 f3 = base[ryc_zc + gxf];   // (f,c,c)
                float2 f4 = base[ryf_zf + gxc];   // (c,f,f)
                float2 f5 = base[ryc_zf + gxf];   // (f,c,f)
                float2 f6 = base[ryf_zc + gxf];   // (f,f,c)
                float2 f7 = base[ryf_zf + gxf];   // (f,f,f)

                float ux = 1.0f - tx, uy = 1.0f - ty, uz = 1.0f - tz;
                float w0 = tx * ty * tz;
                float w1 = tx * uy * tz;
                float w2 = ux * uy * tz;
                float w3 = ux * ty * tz;
                float w4 = tx * ty * uz;
                float w5 = tx * uy * uz;
                float w6 = ux * uy * uz;
                float w7 = ux * ty * uz;

                float ex = 0.f, ey = 0.f;
                ex = fmaf(w0, f0.x, ex); ey = fmaf(w0, f0.y, ey);
                ex = fmaf(w1, f1.x, ex); ey = fmaf(w1, f1.y, ey);
                ex = fmaf(w2, f2.x, ex); ey = fmaf(w2, f2.y, ey);
                ex = fmaf(w3, f3.x, ex); ey = fmaf(w3, f3.y, ey);
                ex = fmaf(w4, f4.x, ex); ey = fmaf(w4, f4.y, ey);
                ex = fmaf(w5, f5.x, ex); ey = fmaf(w5, f5.y, ey);
                ex = fmaf(w6, f6.x, ex); ey = fmaf(w6, f6.y, ey);
                ex = fmaf(w7, f7.x, ex); ey = fmaf(w7, f7.y, ey);
                res[l] = make_float2(ex, ey);
            }
            // two adjacent float2 -> one streaming float4 store
            st_cs_f4((float4*)(out + p * 16),
                     make_float4(res[0].x, res[0].y, res[1].x, res[1].y));
        }
    } else {
        // Fallback: global gathers for levels 0..1 (any table size / scaling)
        for (int p = p_begin + tid; p < p_end; p += COARSE_TPB) {
            float px = __ldg(&x[p * 3 + 0]);
            float py = __ldg(&x[p * 3 + 1]);
            float pz = __ldg(&x[p * 3 + 2]);
            #pragma unroll
            for (int l = 0; l < 2; l++) {
                float s = l ? s1 : s0;
                int off = l ? off1 : off0;
                float sx = px * s, sy = py * s, sz = pz * s;
                float fx = floorf(sx), fy = floorf(sy), fz = floorf(sz);
                float cxx = ceilf(sx), cyy = ceilf(sy), czz = ceilf(sz);
                float tx = sx - fx, ty = sy - fy, tz = sz - fz;

                uint32_t axf = f2u(fx), axc = f2u(cxx);
                uint32_t hyf = f2u(fy) * P1C, hyc = f2u(cyy) * P1C;
                uint32_t hzf = f2u(fz) * P2C, hzc = f2u(czz) * P2C;

                uint32_t hs[8] = {
                    axc ^ hyc ^ hzc, axc ^ hyc ^ hzf, axc ^ hyf ^ hzc, axf ^ hyc ^ hzc,
                    axc ^ hyf ^ hzf, axf ^ hyc ^ hzf, axf ^ hyf ^ hzc, axf ^ hyf ^ hzf };

                float ux = 1.0f - tx, uy = 1.0f - ty, uz = 1.0f - tz;
                float w[8] = {
                    tx * ty * tz, tx * uy * tz, ux * uy * tz, ux * ty * tz,
                    tx * ty * uz, tx * uy * uz, ux * uy * uz, ux * ty * uz };

                float ex = 0.f, ey = 0.f;
                #pragma unroll
                for (int c = 0; c < 8; c++) {
                    int idx = (int)(hs[c] % ts) + off;
                    float2 f = __ldg(&table[idx]);
                    ex = fmaf(w[c], f.x, ex);
                    ey = fmaf(w[c], f.y, ey);
                }
                st_cs_f2(&out[p * 16 + l], make_float2(ex, ey));
            }
        }
    }
}

// ---------------------------------------------------------------------------
// Generic fallback (L != 16)
// ---------------------------------------------------------------------------
__global__ void __launch_bounds__(256)
hashenc_kernel_gen(const float* __restrict__ x,
                   const float2* __restrict__ table,
                   const float* __restrict__ scalings,
                   const int* __restrict__ hash_offset,
                   const int* __restrict__ tsp, int ts_flag,
                   float2* __restrict__ out,
                   int n_points, int L)
{
    int tid = blockIdx.x * 256 + threadIdx.x;
    int level = tid % L;
    int point = tid / L;
    if (point >= n_points) return;

    uint32_t ts = ts_flag ? (uint32_t)__ldg(tsp) : 524288u;

    float px = __ldg(&x[point * 3 + 0]);
    float py = __ldg(&x[point * 3 + 1]);
    float pz = __ldg(&x[point * 3 + 2]);

    float s = __ldg(&scalings[level]);
    int  off = __ldg(&hash_offset[level]);

    float sx = px * s, sy = py * s, sz = pz * s;
    float fx = floorf(sx), fy = floorf(sy), fz = floorf(sz);
    float cx = ceilf(sx), cy = ceilf(sy), cz = ceilf(sz);
    float tx = sx - fx, ty = sy - fy, tz = sz - fz;

    uint32_t hxf = f2u(fx), hxc = f2u(cx);
    uint32_t hyf = f2u(fy) * P1C, hyc = f2u(cy) * P1C;
    uint32_t hzf = f2u(fz) * P2C, hzc = f2u(cz) * P2C;

    uint32_t hs[8] = {
        hxc ^ hyc ^ hzc, hxc ^ hyc ^ hzf, hxc ^ hyf ^ hzc, hxf ^ hyc ^ hzc,
        hxc ^ hyf ^ hzf, hxf ^ hyc ^ hzf, hxf ^ hyf ^ hzc, hxf ^ hyf ^ hzf };

    float ux = 1.0f - tx, uy = 1.0f - ty, uz = 1.0f - tz;
    float w[8] = {
        tx * ty * tz, tx * uy * tz, ux * uy * tz, ux * ty * tz,
        tx * ty * uz, tx * uy * uz, ux * uy * uz, ux * ty * uz };

    float ex = 0.f, ey = 0.f;
    #pragma unroll
    for (int c = 0; c < 8; c++) {
        int idx = (int)(hs[c] % ts) + off;
        float2 f = __ldg(&table[idx]);
        ex = fmaf(w[c], f.x, ex);
        ey = fmaf(w[c], f.y, ey);
    }
    out[point * L + level] = make_float2(ex, ey);
}

extern "C" void kernel_launch(void* const* d_in, const int* in_sizes, int n_in,
                              void* d_out, int out_size)
{
    const float*  x        = (const float*)d_in[0];
    const float2* table    = (const float2*)d_in[1];
    const float*  scalings = (const float*)d_in[2];
    const int*    hoff     = (const int*)d_in[3];
    const int*    tsp      = (n_in >= 5) ? (const int*)d_in[4] : nullptr;
    int ts_flag = (tsp != nullptr) ? 1 : 0;

    int n_points = in_sizes[0] / 3;
    int L = in_sizes[2];

    float2* out = (float2*)d_out;

    if (L == 16) {
        static bool attr_set = false;
        if (!attr_set) {
            cudaFuncSetAttribute(hashenc_coarse,
                                 cudaFuncAttributeMaxDynamicSharedMemorySize,
                                 COARSE_SMEM);
            attr_set = true;
        }

        // Fork a side stream off the capturing main stream so
        // stage -> coarse (stream-ordered) run concurrently with fine.
        cudaStream_t s2;
        cudaEvent_t e1, e2;
        cudaStreamCreateWithFlags(&s2, cudaStreamNonBlocking);
        cudaEventCreateWithFlags(&e1, cudaEventDisableTiming);
        cudaEventCreateWithFlags(&e2, cudaEventDisableTiming);

        cudaEventRecord(e1, 0);
        cudaStreamWaitEvent(s2, e1, 0);

        hashenc_stage<<<68, 256, 0, s2>>>(table, scalings, hoff, tsp, ts_flag);

        int pts_per_cta = (n_points + COARSE_BLOCKS - 1) / COARSE_BLOCKS;
        hashenc_coarse<<<COARSE_BLOCKS, COARSE_TPB, COARSE_SMEM, s2>>>(
            x, table, scalings, hoff, tsp, ts_flag, out, n_points, pts_per_cta);

        int fine_blocks = (n_points + 15) / 16;
        hashenc_fine<<<fine_blocks, 224>>>(
            x, table, scalings, hoff, tsp, ts_flag, out, n_points);

        cudaEventRecord(e2, s2);
        cudaStreamWaitEvent(0, e2, 0);
    } else {
        long long total = (long long)n_points * L;
        int blocks = (int)((total + 255) / 256);
        hashenc_kernel_gen<<<blocks, 256>>>(x, table, scalings, hoff, tsp, ts_flag,
                                            out, n_points, L);
    }
}

// round 12
// speedup vs baseline: 1.2504x; 1.0286x over previous
#include <cuda_runtime.h>
#include <stdint.h>

#define P1C 2654435761u
#define P2C 805459861u

// smem dense grids for levels 0,1 (fp32 float2): 17^3 + 23^3
#define CAP0 4913
#define CAP1 12167
#define COARSE_SMEM ((CAP0 + CAP1) * 8)
#define COARSE_BLOCKS 64
#define COARSE_TPB 256

__device__ __forceinline__ uint32_t f2u(float f) {
    return (uint32_t)(int32_t)f;
}

// ---------------------------------------------------------------------------
// Fine kernel: levels 2..15, one thread per (point, level).
// blockDim = 224 = 16 points * 14 levels.  (137.5-138us measured — at the
// L1 line-touch roofline: 6 lines per (pt,lvl) avg, ~1.08 lines/cyc/SM.)
// ---------------------------------------------------------------------------
__global__ void __launch_bounds__(224)
hashenc_fine(const float* __restrict__ x,
             const float2* __restrict__ table,
             const float* __restrict__ scalings,
             const int* __restrict__ hash_offset,
             const int* __restrict__ tsp, int ts_flag,
             float2* __restrict__ out,
             int n_points)
{
    int local = threadIdx.x;
    int pib   = local / 14;               // point in block [0,16)
    int level = 2 + (local - pib * 14);   // [2,16)
    int point = blockIdx.x * 16 + pib;
    if (point >= n_points) return;

    uint32_t ts = ts_flag ? (uint32_t)__ldg(tsp) : 524288u;
    bool pow2 = (ts & (ts - 1u)) == 0u;
    uint32_t mask = ts - 1u;

    float px = __ldg(&x[point * 3 + 0]);
    float py = __ldg(&x[point * 3 + 1]);
    float pz = __ldg(&x[point * 3 + 2]);

    float s = __ldg(&scalings[level]);
    int  off = __ldg(&hash_offset[level]);

    float sx = px * s, sy = py * s, sz = pz * s;
    float fx = floorf(sx), fy = floorf(sy), fz = floorf(sz);
    float cx = ceilf(sx), cy = ceilf(sy), cz = ceilf(sz);
    float tx = sx - fx, ty = sy - fy, tz = sz - fz;

    uint32_t axf = f2u(fx);
    uint32_t axc = f2u(cx);
    uint32_t hyf = f2u(fy) * P1C;
    uint32_t hyc = f2u(cy) * P1C;
    uint32_t hzf = f2u(fz) * P2C;
    uint32_t hzc = f2u(cz) * P2C;

    float ux = 1.0f - tx, uy = 1.0f - ty, uz = 1.0f - tz;
    // EXACT reference weight<->corner pairing (tz quirk preserved)
    float w0 = tx * ty * tz;   // (c,c,c)
    float w1 = tx * uy * tz;   // (c,c,f)
    float w2 = ux * uy * tz;   // (c,f,c)
    float w3 = ux * ty * tz;   // (f,c,c)
    float w4 = tx * ty * uz;   // (c,f,f)
    float w5 = tx * uy * uz;   // (f,c,f)
    float w6 = ux * uy * uz;   // (f,f,c)
    float w7 = ux * ty * uz;   // (f,f,f)

    float ex = 0.f, ey = 0.f;

    if (pow2 && ((axf ^ axc) == 1u)) {
        // x floor/ceil pair shares one aligned 16B float4 chunk.
        const float4* __restrict__ t4 = (const float4*)table;
        uint32_t off2 = ((uint32_t)off) >> 1;

        uint32_t b0 = hyc ^ hzc;   // pair (v0 ceil-x, v3 floor-x)
        uint32_t b1 = hyc ^ hzf;   // pair (v1, v5)
        uint32_t b2 = hyf ^ hzc;   // pair (v2, v6)
        uint32_t b3 = hyf ^ hzf;   // pair (v4, v7)

        uint32_t i0 = (axf ^ b0) & mask;
        uint32_t i1 = (axf ^ b1) & mask;
        uint32_t i2 = (axf ^ b2) & mask;
        uint32_t i3 = (axf ^ b3) & mask;

        float4 q0 = __ldg(&t4[(i0 >> 1) + off2]);
        float4 q1 = __ldg(&t4[(i1 >> 1) + off2]);
        float4 q2 = __ldg(&t4[(i2 >> 1) + off2]);
        float4 q3 = __ldg(&t4[(i3 >> 1) + off2]);

        {
            uint32_t sel = i0 & 1u;
            float ffx = sel ? q0.z : q0.x, ffy = sel ? q0.w : q0.y;
            float fcx = sel ? q0.x : q0.z, fcy = sel ? q0.y : q0.w;
            ex = fmaf(w3, ffx, ex); ey = fmaf(w3, ffy, ey);
            ex = fmaf(w0, fcx, ex); ey = fmaf(w0, fcy, ey);
        }
        {
            uint32_t sel = i1 & 1u;
            float ffx = sel ? q1.z : q1.x, ffy = sel ? q1.w : q1.y;
            float fcx = sel ? q1.x : q1.z, fcy = sel ? q1.y : q1.w;
            ex = fmaf(w5, ffx, ex); ey = fmaf(w5, ffy, ey);
            ex = fmaf(w1, fcx, ex); ey = fmaf(w1, fcy, ey);
        }
        {
            uint32_t sel = i2 & 1u;
            float ffx = sel ? q2.z : q2.x, ffy = sel ? q2.w : q2.y;
            float fcx = sel ? q2.x : q2.z, fcy = sel ? q2.y : q2.w;
            ex = fmaf(w6, ffx, ex); ey = fmaf(w6, ffy, ey);
            ex = fmaf(w2, fcx, ex); ey = fmaf(w2, fcy, ey);
        }
        {
            uint32_t sel = i3 & 1u;
            float ffx = sel ? q3.z : q3.x, ffy = sel ? q3.w : q3.y;
            float fcx = sel ? q3.x : q3.z, fcy = sel ? q3.y : q3.w;
            ex = fmaf(w7, ffx, ex); ey = fmaf(w7, ffy, ey);
            ex = fmaf(w4, fcx, ex); ey = fmaf(w4, fcy, ey);
        }
    } else {
        uint32_t h0 = axc ^ hyc ^ hzc;
        uint32_t h1 = axc ^ hyc ^ hzf;
        uint32_t h2 = axc ^ hyf ^ hzc;
        uint32_t h3 = axf ^ hyc ^ hzc;
        uint32_t h4 = axc ^ hyf ^ hzf;
        uint32_t h5 = axf ^ hyc ^ hzf;
        uint32_t h6 = axf ^ hyf ^ hzc;
        uint32_t h7 = axf ^ hyf ^ hzf;

        int i0, i1, i2, i3, i4, i5, i6, i7;
        if (pow2) {
            i0 = (int)(h0 & mask) + off;  i1 = (int)(h1 & mask) + off;
            i2 = (int)(h2 & mask) + off;  i3 = (int)(h3 & mask) + off;
            i4 = (int)(h4 & mask) + off;  i5 = (int)(h5 & mask) + off;
            i6 = (int)(h6 & mask) + off;  i7 = (int)(h7 & mask) + off;
        } else {
            i0 = (int)(h0 % ts) + off;    i1 = (int)(h1 % ts) + off;
            i2 = (int)(h2 % ts) + off;    i3 = (int)(h3 % ts) + off;
            i4 = (int)(h4 % ts) + off;    i5 = (int)(h5 % ts) + off;
            i6 = (int)(h6 % ts) + off;    i7 = (int)(h7 % ts) + off;
        }

        float2 f0 = __ldg(&table[i0]);
        float2 f1 = __ldg(&table[i1]);
        float2 f2 = __ldg(&table[i2]);
        float2 f3 = __ldg(&table[i3]);
        float2 f4 = __ldg(&table[i4]);
        float2 f5 = __ldg(&table[i5]);
        float2 f6 = __ldg(&table[i6]);
        float2 f7 = __ldg(&table[i7]);

        ex = fmaf(w0, f0.x, ex); ey = fmaf(w0, f0.y, ey);
        ex = fmaf(w1, f1.x, ex); ey = fmaf(w1, f1.y, ey);
        ex = fmaf(w2, f2.x, ex); ey = fmaf(w2, f2.y, ey);
        ex = fmaf(w3, f3.x, ex); ey = fmaf(w3, f3.y, ey);
        ex = fmaf(w4, f4.x, ex); ey = fmaf(w4, f4.y, ey);
        ex = fmaf(w5, f5.x, ex); ey = fmaf(w5, f5.y, ey);
        ex = fmaf(w6, f6.x, ex); ey = fmaf(w6, f6.y, ey);
        ex = fmaf(w7, f7.x, ex); ey = fmaf(w7, f7.y, ey);
    }

    out[point * 16 + level] = make_float2(ex, ey);
}

// ---------------------------------------------------------------------------
// Coarse kernel: levels 0..1 via smem-resident dense fp32 grids.
// 64 CTAs @256 (R8-proven config, +9.5us wall delta = work displacement).
// Paired LDG.128 preload + pow2 mask.
// ---------------------------------------------------------------------------
__global__ void __launch_bounds__(COARSE_TPB)
hashenc_coarse(const float* __restrict__ x,
               const float2* __restrict__ table,
               const float* __restrict__ scalings,
               const int* __restrict__ hash_offset,
               const int* __restrict__ tsp, int ts_flag,
               float2* __restrict__ out,
               int n_points, int pts_per_cta)
{
    extern __shared__ float2 sm[];   // [n0 + n1]

    uint32_t ts = ts_flag ? (uint32_t)__ldg(tsp) : 524288u;
    bool pow2 = (ts & (ts - 1u)) == 0u;
    uint32_t mask = ts - 1u;

    float s0 = __ldg(&scalings[0]);
    float s1 = __ldg(&scalings[1]);
    int off0 = __ldg(&hash_offset[0]);
    int off1 = __ldg(&hash_offset[1]);
    int d0 = (int)s0 + 1;
    int d1 = (int)s1 + 1;
    int n0 = d0 * d0 * d0;
    int n1 = d1 * d1 * d1;

    int tid = threadIdx.x;
    int p_begin = blockIdx.x * pts_per_cta;
    int p_end = p_begin + pts_per_cta;
    if (p_end > n_points) p_end = n_points;

    bool ok = (n0 <= CAP0) && (n1 <= CAP1) && (d0 > 1) && (d1 > 1);

    if (ok) {
        const float4* __restrict__ t4 = (const float4*)table;
        // --- preload levels 0,1 ---
        #pragma unroll
        for (int l = 0; l < 2; l++) {
            int d = l ? d1 : d0;
            int off = l ? off1 : off0;
            float2* g = sm + (l ? n0 : 0);
            if (pow2) {
                // paired: even gx and gx+1 share one 16B chunk
                int ppr = d >> 1;
                int npairs = d * d * ppr;
                uint32_t off2 = ((uint32_t)off) >> 1;
                for (int id = tid; id < npairs; id += COARSE_TPB) {
                    int rowid = id / ppr;
                    int gx = (id - rowid * ppr) * 2;
                    int gy = rowid % d;
                    int gz = rowid / d;
                    uint32_t h = ((uint32_t)gx ^ ((uint32_t)gy * P1C) ^ ((uint32_t)gz * P2C)) & mask;
                    float4 q = __ldg(&t4[(h >> 1) + off2]);
                    int base = (gz * d + gy) * d + gx;
                    bool hodd = h & 1u;
                    g[base]     = hodd ? make_float2(q.z, q.w) : make_float2(q.x, q.y);
                    g[base + 1] = hodd ? make_float2(q.x, q.y) : make_float2(q.z, q.w);
                }
                if (d & 1) {   // last column when d is odd
                    int gx = d - 1;
                    for (int id = tid; id < d * d; id += COARSE_TPB) {
                        int gy = id % d, gz = id / d;
                        uint32_t h = ((uint32_t)gx ^ ((uint32_t)gy * P1C) ^ ((uint32_t)gz * P2C)) & mask;
                        g[(gz * d + gy) * d + gx] = __ldg(&table[(int)h + off]);
                    }
                }
            } else {
                int n = d * d * d;
                for (int id = tid; id < n; id += COARSE_TPB) {
                    int gz = id / (d * d);
                    int r  = id - gz * d * d;
                    int gy = r / d;
                    int gx = r - gy * d;
                    uint32_t h = ((uint32_t)gx ^ ((uint32_t)gy * P1C) ^ ((uint32_t)gz * P2C)) % ts;
                    g[id] = __ldg(&table[(int)h + off]);
                }
            }
        }
        __syncthreads();

        for (int p = p_begin + tid; p < p_end; p += COARSE_TPB) {
            float px = __ldg(&x[p * 3 + 0]);
            float py = __ldg(&x[p * 3 + 1]);
            float pz = __ldg(&x[p * 3 + 2]);

            float2 res[2];
            #pragma unroll
            for (int l = 0; l < 2; l++) {
                float s = l ? s1 : s0;
                int dim = l ? d1 : d0;
                const float2* base = l ? (sm + n0) : sm;

                float sx = px * s, sy = py * s, sz = pz * s;
                float fx = floorf(sx), fy = floorf(sy), fz = floorf(sz);
                float cxx = ceilf(sx), cyy = ceilf(sy), czz = ceilf(sz);
                float tx = sx - fx, ty = sy - fy, tz = sz - fz;

                int gxf = (int)fx, gxc = (int)cxx;
                int gyf = (int)fy, gyc = (int)cyy;
                int gzf = (int)fz, gzc = (int)czz;

                int ryc_zc = (gzc * dim + gyc) * dim;
                int ryc_zf = (gzf * dim + gyc) * dim;
                int ryf_zc = (gzc * dim + gyf) * dim;
                int ryf_zf = (gzf * dim + gyf) * dim;

                float2 f0 = base[ryc_zc + gxc];   // (c,c,c)
                float2 f1 = base[ryc_zf + gxc];   // (c,c,f)
                float2 f2 = base[ryf_zc + gxc];   // (c,f,c)
                float2 f3 = base[ryc_zc + gxf];   // (f,c,c)
                float2 f4 = base[ryf_zf + gxc];   // (c,f,f)
                float2 f5 = base[ryc_zf + gxf];   // (f,c,f)
                float2 f6 = base[ryf_zc + gxf];   // (f,f,c)
                float2 f7 = base[ryf_zf + gxf];   // (f,f,f)

                float ux = 1.0f - tx, uy = 1.0f - ty, uz = 1.0f - tz;
                float w0 = tx * ty * tz;
                float w1 = tx * uy * tz;
                float w2 = ux * uy * tz;
                float w3 = ux * ty * tz;
                float w4 = tx * ty * uz;
                float w5 = tx * uy * uz;
                float w6 = ux * uy * uz;
                float w7 = ux * ty * uz;

                float ex = 0.f, ey = 0.f;
                ex = fmaf(w0, f0.x, ex); ey = fmaf(w0, f0.y, ey);
                ex = fmaf(w1, f1.x, ex); ey = fmaf(w1, f1.y, ey);
                ex = fmaf(w2, f2.x, ex); ey = fmaf(w2, f2.y, ey);
                ex = fmaf(w3, f3.x, ex); ey = fmaf(w3, f3.y, ey);
                ex = fmaf(w4, f4.x, ex); ey = fmaf(w4, f4.y, ey);
                ex = fmaf(w5, f5.x, ex); ey = fmaf(w5, f5.y, ey);
                ex = fmaf(w6, f6.x, ex); ey = fmaf(w6, f6.y, ey);
                ex = fmaf(w7, f7.x, ex); ey = fmaf(w7, f7.y, ey);
                res[l] = make_float2(ex, ey);
            }
            // two adjacent float2 -> one float4 store
            float4* o4 = (float4*)(out + p * 16);
            *o4 = make_float4(res[0].x, res[0].y, res[1].x, res[1].y);
        }
    } else {
        // Fallback: global gathers for levels 0..1 (any table size / scaling)
        for (int p = p_begin + tid; p < p_end; p += COARSE_TPB) {
            float px = __ldg(&x[p * 3 + 0]);
            float py = __ldg(&x[p * 3 + 1]);
            float pz = __ldg(&x[p * 3 + 2]);
            #pragma unroll
            for (int l = 0; l < 2; l++) {
                float s = l ? s1 : s0;
                int off = l ? off1 : off0;
                float sx = px * s, sy = py * s, sz = pz * s;
                float fx = floorf(sx), fy = floorf(sy), fz = floorf(sz);
                float cxx = ceilf(sx), cyy = ceilf(sy), czz = ceilf(sz);
                float tx = sx - fx, ty = sy - fy, tz = sz - fz;

                uint32_t axf = f2u(fx), axc = f2u(cxx);
                uint32_t hyf = f2u(fy) * P1C, hyc = f2u(cyy) * P1C;
                uint32_t hzf = f2u(fz) * P2C, hzc = f2u(czz) * P2C;

                uint32_t hs[8] = {
                    axc ^ hyc ^ hzc, axc ^ hyc ^ hzf, axc ^ hyf ^ hzc, axf ^ hyc ^ hzc,
                    axc ^ hyf ^ hzf, axf ^ hyc ^ hzf, axf ^ hyf ^ hzc, axf ^ hyf ^ hzf };

                float ux = 1.0f - tx, uy = 1.0f - ty, uz = 1.0f - tz;
                float w[8] = {
                    tx * ty * tz, tx * uy * tz, ux * uy * tz, ux * ty * tz,
                    tx * ty * uz, tx * uy * uz, ux * uy * uz, ux * ty * uz };

                float ex = 0.f, ey = 0.f;
                #pragma unroll
                for (int c = 0; c < 8; c++) {
                    int idx = (int)(hs[c] % ts) + off;
                    float2 f = __ldg(&table[idx]);
                    ex = fmaf(w[c], f.x, ex);
                    ey = fmaf(w[c], f.y, ey);
                }
                out[p * 16 + l] = make_float2(ex, ey);
            }
        }
    }
}

// ---------------------------------------------------------------------------
// Generic fallback (L != 16)
// ---------------------------------------------------------------------------
__global__ void __launch_bounds__(256)
hashenc_kernel_gen(const float* __restrict__ x,
                   const float2* __restrict__ table,
                   const float* __restrict__ scalings,
                   const int* __restrict__ hash_offset,
                   const int* __restrict__ tsp, int ts_flag,
                   float2* __restrict__ out,
                   int n_points, int L)
{
    int tid = blockIdx.x * 256 + threadIdx.x;
    int level = tid % L;
    int point = tid / L;
    if (point >= n_points) return;

    uint32_t ts = ts_flag ? (uint32_t)__ldg(tsp) : 524288u;

    float px = __ldg(&x[point * 3 + 0]);
    float py = __ldg(&x[point * 3 + 1]);
    float pz = __ldg(&x[point * 3 + 2]);

    float s = __ldg(&scalings[level]);
    int  off = __ldg(&hash_offset[level]);

    float sx = px * s, sy = py * s, sz = pz * s;
    float fx = floorf(sx), fy = floorf(sy), fz = floorf(sz);
    float cx = ceilf(sx), cy = ceilf(sy), cz = ceilf(sz);
    float tx = sx - fx, ty = sy - fy, tz = sz - fz;

    uint32_t hxf = f2u(fx), hxc = f2u(cx);
    uint32_t hyf = f2u(fy) * P1C, hyc = f2u(cy) * P1C;
    uint32_t hzf = f2u(fz) * P2C, hzc = f2u(cz) * P2C;

    uint32_t hs[8] = {
        hxc ^ hyc ^ hzc, hxc ^ hyc ^ hzf, hxc ^ hyf ^ hzc, hxf ^ hyc ^ hzc,
        hxc ^ hyf ^ hzf, hxf ^ hyc ^ hzf, hxf ^ hyf ^ hzc, hxf ^ hyf ^ hzf };

    float ux = 1.0f - tx, uy = 1.0f - ty, uz = 1.0f - tz;
    float w[8] = {
        tx * ty * tz, tx * uy * tz, ux * uy * tz, ux * ty * tz,
        tx * ty * uz, tx * uy * uz, ux * uy * uz, ux * ty * uz };

    float ex = 0.f, ey = 0.f;
    #pragma unroll
    for (int c = 0; c < 8; c++) {
        int idx = (int)(hs[c] % ts) + off;
        float2 f = __ldg(&table[idx]);
        ex = fmaf(w[c], f.x, ex);
        ey = fmaf(w[c], f.y, ey);
    }
    out[point * L + level] = make_float2(ex, ey);
}

extern "C" void kernel_launch(void* const* d_in, const int* in_sizes, int n_in,
                              void* d_out, int out_size)
{
    const float*  x        = (const float*)d_in[0];
    const float2* table    = (const float2*)d_in[1];
    const float*  scalings = (const float*)d_in[2];
    const int*    hoff     = (const int*)d_in[3];
    const int*    tsp      = (n_in >= 5) ? (const int*)d_in[4] : nullptr;
    int ts_flag = (tsp != nullptr) ? 1 : 0;

    int n_points = in_sizes[0] / 3;
    int L = in_sizes[2];

    float2* out = (float2*)d_out;

    if (L == 16) {
        static bool attr_set = false;
        if (!attr_set) {
            cudaFuncSetAttribute(hashenc_coarse,
                                 cudaFuncAttributeMaxDynamicSharedMemorySize,
                                 COARSE_SMEM);
            attr_set = true;
        }

        // Fork a side stream off the capturing main stream so coarse runs
        // concurrently with fine (R8-proven structure).
        cudaStream_t s2;
        cudaEvent_t e1, e2;
        cudaStreamCreateWithFlags(&s2, cudaStreamNonBlocking);
        cudaEventCreateWithFlags(&e1, cudaEventDisableTiming);
        cudaEventCreateWithFlags(&e2, cudaEventDisableTiming);

        cudaEventRecord(e1, 0);
        cudaStreamWaitEvent(s2, e1, 0);

        int pts_per_cta = (n_points + COARSE_BLOCKS - 1) / COARSE_BLOCKS;
        hashenc_coarse<<<COARSE_BLOCKS, COARSE_TPB, COARSE_SMEM, s2>>>(
            x, table, scalings, hoff, tsp, ts_flag, out, n_points, pts_per_cta);

        int fine_blocks = (n_points + 15) / 16;
        hashenc_fine<<<fine_blocks, 224>>>(
            x, table, scalings, hoff, tsp, ts_flag, out, n_points);

        cudaEventRecord(e2, s2);
        cudaStreamWaitEvent(0, e2, 0);
    } else {
        long long total = (long long)n_points * L;
        int blocks = (int)((total + 255) / 256);
        hashenc_kernel_gen<<<blocks, 256>>>(x, table, scalings, hoff, tsp, ts_flag,
                                            out, n_points, L);
    }
}